// round 13
// baseline (speedup 1.0000x reference)
#include <cuda_runtime.h>
#include <math.h>

// ---------------------------------------------------------------------------
// AV_Attention: B=8, S=2048, INPUT_DIM=1024, DIM_K=DIM_V=1024, fp32.
//   Q = img @ q_w^T + q_b ; K = text @ k_w^T + k_b ; V = text @ v_w^T + v_b
//   scores = Q @ K^T (per batch)  [NO pre-softmax scaling — quirk!]
//   atten  = softmax(scores) * (1/sqrt(1024))
//   output = atten @ V ; feature = output + text
// Outputs flattened: d_out[0:16777216)=output, d_out[16777216:33554432)=feature
// ---------------------------------------------------------------------------

static __device__ float g_Q[16777216];   // 64 MB
static __device__ float g_K[16777216];   // 64 MB
static __device__ float g_V[16777216];   // 64 MB
static __device__ float g_S[33554432];   // 128 MB (scores / atten)

constexpr int BM = 128, BN = 128, BK = 16;

// ---------------------------------------------------------------------------
// Generic 128x128x16 double-buffered SGEMM.
//  C = A @ B^T (TRANSB=true, B is [N,K] row-major)   or
//  C = A @ B   (TRANSB=false, B is [K,N] row-major)
//  BIAS : add bias[col]
//  AVEPI: write C and feat = C + text
// Grid: (N/128, M/128, batches). All dims must divide the tiles (they do).
// ---------------------------------------------------------------------------
template <bool TRANSB, bool BIAS, bool AVEPI>
__global__ void __launch_bounds__(256, 2)
gemm_k(const float* __restrict__ A, const float* __restrict__ B,
       const float* __restrict__ bias, float* __restrict__ C,
       const float* __restrict__ text, float* __restrict__ feat,
       int K, int lda, int ldb, int ldc,
       long long sA, long long sB, long long sC)
{
    __shared__ float As[2][BK][BM + 4];
    __shared__ float Bs[2][BK][BN + 4];

    const int z = blockIdx.z;
    A += (long long)z * sA;
    B += (long long)z * sB;
    C += (long long)z * sC;
    if (AVEPI) { text += (long long)z * sC; feat += (long long)z * sC; }

    const int tid = threadIdx.x;
    const int tx = tid & 15;
    const int ty = tid >> 4;
    const int bx = blockIdx.x, by = blockIdx.y;

    // A loader: 128 rows x 16 k, transpose-store. 2 float4 per thread.
    const int arow = tid >> 2;            // 0..63
    const int acol = (tid & 3) << 2;      // 0,4,8,12
    const float* Aptr0 = A + (long long)(by * BM + arow) * lda + acol;
    const float* Aptr1 = Aptr0 + 64LL * lda;

    // B loader
    const float* Bptr0;
    const float* Bptr1;
    int bk_row = 0, bn_col = 0;
    if (TRANSB) {
        Bptr0 = B + (long long)(bx * BN + arow) * ldb + acol;
        Bptr1 = Bptr0 + 64LL * ldb;
    } else {
        bk_row = tid >> 5;                // 0..7
        bn_col = (tid & 31) << 2;         // 0..124
        Bptr0 = B + (long long)bk_row * ldb + bx * BN + bn_col;
        Bptr1 = Bptr0 + 8LL * ldb;
    }

    auto ld_tile = [&](int k0, float4& va0, float4& va1, float4& vb0, float4& vb1) {
        va0 = *reinterpret_cast<const float4*>(Aptr0 + k0);
        va1 = *reinterpret_cast<const float4*>(Aptr1 + k0);
        if (TRANSB) {
            vb0 = *reinterpret_cast<const float4*>(Bptr0 + k0);
            vb1 = *reinterpret_cast<const float4*>(Bptr1 + k0);
        } else {
            vb0 = *reinterpret_cast<const float4*>(Bptr0 + (long long)k0 * ldb);
            vb1 = *reinterpret_cast<const float4*>(Bptr1 + (long long)k0 * ldb);
        }
    };

    auto st_tile = [&](int s, float4 va0, float4 va1, float4 vb0, float4 vb1) {
        As[s][acol + 0][arow] = va0.x;
        As[s][acol + 1][arow] = va0.y;
        As[s][acol + 2][arow] = va0.z;
        As[s][acol + 3][arow] = va0.w;
        As[s][acol + 0][arow + 64] = va1.x;
        As[s][acol + 1][arow + 64] = va1.y;
        As[s][acol + 2][arow + 64] = va1.z;
        As[s][acol + 3][arow + 64] = va1.w;
        if (TRANSB) {
            Bs[s][acol + 0][arow] = vb0.x;
            Bs[s][acol + 1][arow] = vb0.y;
            Bs[s][acol + 2][arow] = vb0.z;
            Bs[s][acol + 3][arow] = vb0.w;
            Bs[s][acol + 0][arow + 64] = vb1.x;
            Bs[s][acol + 1][arow + 64] = vb1.y;
            Bs[s][acol + 2][arow + 64] = vb1.z;
            Bs[s][acol + 3][arow + 64] = vb1.w;
        } else {
            *reinterpret_cast<float4*>(&Bs[s][bk_row][bn_col]) = vb0;
            *reinterpret_cast<float4*>(&Bs[s][bk_row + 8][bn_col]) = vb1;
        }
    };

    float acc[8][8];
#pragma unroll
    for (int i = 0; i < 8; ++i)
#pragma unroll
        for (int j = 0; j < 8; ++j) acc[i][j] = 0.0f;

    {
        float4 a0, a1, b0, b1;
        ld_tile(0, a0, a1, b0, b1);
        st_tile(0, a0, a1, b0, b1);
    }
    __syncthreads();

    const int nk = K / BK;
    for (int kt = 0; kt < nk; ++kt) {
        const int s = kt & 1;
        float4 na0, na1, nb0, nb1;
        const bool pf = (kt + 1 < nk);
        if (pf) ld_tile((kt + 1) * BK, na0, na1, nb0, nb1);

#pragma unroll
        for (int kk = 0; kk < BK; ++kk) {
            float4 xa0 = *reinterpret_cast<const float4*>(&As[s][kk][ty * 8]);
            float4 xa1 = *reinterpret_cast<const float4*>(&As[s][kk][ty * 8 + 4]);
            float4 xb0 = *reinterpret_cast<const float4*>(&Bs[s][kk][tx * 8]);
            float4 xb1 = *reinterpret_cast<const float4*>(&Bs[s][kk][tx * 8 + 4]);
            float ar[8] = {xa0.x, xa0.y, xa0.z, xa0.w, xa1.x, xa1.y, xa1.z, xa1.w};
            float br[8] = {xb0.x, xb0.y, xb0.z, xb0.w, xb1.x, xb1.y, xb1.z, xb1.w};
#pragma unroll
            for (int i = 0; i < 8; ++i)
#pragma unroll
                for (int j = 0; j < 8; ++j)
                    acc[i][j] = fmaf(ar[i], br[j], acc[i][j]);
        }

        if (pf) st_tile(s ^ 1, na0, na1, nb0, nb1);
        __syncthreads();
    }

    // Epilogue
    const int row0 = by * BM + ty * 8;
    const int col0 = bx * BN + tx * 8;
    float4 bi0, bi1;
    if (BIAS) {
        bi0 = *reinterpret_cast<const float4*>(bias + col0);
        bi1 = *reinterpret_cast<const float4*>(bias + col0 + 4);
    }
#pragma unroll
    for (int i = 0; i < 8; ++i) {
        const long long off = (long long)(row0 + i) * ldc + col0;
        float4 c0 = make_float4(acc[i][0], acc[i][1], acc[i][2], acc[i][3]);
        float4 c1 = make_float4(acc[i][4], acc[i][5], acc[i][6], acc[i][7]);
        if (BIAS) {
            c0.x += bi0.x; c0.y += bi0.y; c0.z += bi0.z; c0.w += bi0.w;
            c1.x += bi1.x; c1.y += bi1.y; c1.z += bi1.z; c1.w += bi1.w;
        }
        *reinterpret_cast<float4*>(C + off) = c0;
        *reinterpret_cast<float4*>(C + off + 4) = c1;
        if (AVEPI) {
            float4 t0 = *reinterpret_cast<const float4*>(text + off);
            float4 t1 = *reinterpret_cast<const float4*>(text + off + 4);
            float4 f0 = make_float4(c0.x + t0.x, c0.y + t0.y, c0.z + t0.z, c0.w + t0.w);
            float4 f1 = make_float4(c1.x + t1.x, c1.y + t1.y, c1.z + t1.z, c1.w + t1.w);
            *reinterpret_cast<float4*>(feat + off) = f0;
            *reinterpret_cast<float4*>(feat + off + 4) = f1;
        }
    }
}

// ---------------------------------------------------------------------------
// Row softmax over 2048 columns, in place, fused * (1/sqrt(1024)).
// One CTA (256 threads) per row; 8 elements/thread kept in registers.
// ---------------------------------------------------------------------------
__global__ void __launch_bounds__(256) softmax_k(float* __restrict__ Sm)
{
    __shared__ float red[32];
    const long long row = blockIdx.x;
    float* p = Sm + row * 2048;
    const int t = threadIdx.x;
    const int lane = t & 31, w = t >> 5;

    float4 v0 = reinterpret_cast<const float4*>(p)[t];
    float4 v1 = reinterpret_cast<const float4*>(p)[t + 256];

    float m = fmaxf(fmaxf(fmaxf(v0.x, v0.y), fmaxf(v0.z, v0.w)),
                    fmaxf(fmaxf(v1.x, v1.y), fmaxf(v1.z, v1.w)));
#pragma unroll
    for (int o = 16; o > 0; o >>= 1) m = fmaxf(m, __shfl_xor_sync(0xFFFFFFFFu, m, o));
    if (lane == 0) red[w] = m;
    __syncthreads();
    if (t < 32) {
        float x = (t < 8) ? red[t] : -3.4e38f;
#pragma unroll
        for (int o = 4; o > 0; o >>= 1) x = fmaxf(x, __shfl_xor_sync(0xFFFFFFFFu, x, o));
        if (t == 0) red[0] = x;
    }
    __syncthreads();
    m = red[0];
    __syncthreads();   // protect red[] reuse

    float e[8];
    e[0] = expf(v0.x - m); e[1] = expf(v0.y - m); e[2] = expf(v0.z - m); e[3] = expf(v0.w - m);
    e[4] = expf(v1.x - m); e[5] = expf(v1.y - m); e[6] = expf(v1.z - m); e[7] = expf(v1.w - m);
    float s = ((e[0] + e[1]) + (e[2] + e[3])) + ((e[4] + e[5]) + (e[6] + e[7]));
#pragma unroll
    for (int o = 16; o > 0; o >>= 1) s += __shfl_xor_sync(0xFFFFFFFFu, s, o);
    if (lane == 0) red[w] = s;
    __syncthreads();
    if (t < 32) {
        float x = (t < 8) ? red[t] : 0.0f;
#pragma unroll
        for (int o = 4; o > 0; o >>= 1) x += __shfl_xor_sync(0xFFFFFFFFu, x, o);
        if (t == 0) red[0] = x;
    }
    __syncthreads();
    s = red[0];

    const float inv = 0.03125f / s;   // (1/sqrt(1024)) / sum
    float4 o0 = make_float4(e[0] * inv, e[1] * inv, e[2] * inv, e[3] * inv);
    float4 o1 = make_float4(e[4] * inv, e[5] * inv, e[6] * inv, e[7] * inv);
    reinterpret_cast<float4*>(p)[t] = o0;
    reinterpret_cast<float4*>(p)[t + 256] = o1;
}

// ---------------------------------------------------------------------------
extern "C" void kernel_launch(void* const* d_in, const int* in_sizes, int n_in,
                              void* d_out, int out_size)
{
    const float* img  = (const float*)d_in[0];
    const float* text = (const float*)d_in[1];
    const float* q_w  = (const float*)d_in[2];
    const float* q_b  = (const float*)d_in[3];
    const float* k_w  = (const float*)d_in[4];
    const float* k_b  = (const float*)d_in[5];
    const float* v_w  = (const float*)d_in[6];
    const float* v_b  = (const float*)d_in[7];
    float* out = (float*)d_out;

    float *gq, *gk, *gv, *gs;
    cudaGetSymbolAddress((void**)&gq, g_Q);
    cudaGetSymbolAddress((void**)&gk, g_K);
    cudaGetSymbolAddress((void**)&gv, g_V);
    cudaGetSymbolAddress((void**)&gs, g_S);

    const dim3 blk(256);

    // --- Phase A: Q/K/V projections, [16384,1024] = X @ W^T + b ---
    const dim3 gA(1024 / BN, 16384 / BM, 1);
    gemm_k<true, true, false><<<gA, blk>>>(img,  q_w, q_b, gq, nullptr, nullptr,
                                           1024, 1024, 1024, 1024, 0, 0, 0);
    gemm_k<true, true, false><<<gA, blk>>>(text, k_w, k_b, gk, nullptr, nullptr,
                                           1024, 1024, 1024, 1024, 0, 0, 0);
    gemm_k<true, true, false><<<gA, blk>>>(text, v_w, v_b, gv, nullptr, nullptr,
                                           1024, 1024, 1024, 1024, 0, 0, 0);

    // --- Phase B: scores[b] = Q_b @ K_b^T, [2048,2048], K=1024, 8 batches ---
    const dim3 gB(2048 / BN, 2048 / BM, 8);
    gemm_k<true, false, false><<<gB, blk>>>(gq, gk, nullptr, gs, nullptr, nullptr,
                                            1024, 1024, 1024, 2048,
                                            2048LL * 1024, 2048LL * 1024, 2048LL * 2048);

    // --- Phase C: row softmax * 1/32, in place on scores ---
    softmax_k<<<8 * 2048, 256>>>(gs);

    // --- Phase D: output[b] = atten_b @ V_b ; feature = output + text ---
    const dim3 gD(1024 / BN, 2048 / BM, 8);
    gemm_k<false, false, true><<<gD, blk>>>(gs, gv, nullptr,
                                            out, text, out + 16777216LL,
                                            2048, 2048, 1024, 1024,
                                            2048LL * 2048, 2048LL * 1024, 2048LL * 1024);

    (void)in_sizes; (void)n_in; (void)out_size;
}

// round 15
// speedup vs baseline: 2.0845x; 2.0845x over previous
#include <cuda_runtime.h>
#include <cuda_bf16.h>
#include <cstdint>
#include <math.h>

// ---------------------------------------------------------------------------
// AV_Attention via legacy mma.sync bf16x3 (2-split, 3-product) emulated-fp32.
//   Q  = img @ q_w^T + q_b                      [16384,1024]
//   K  = text @ k_w^T + k_b                     [16384,1024]
//   VT = v_w @ text^T + v_b(row)  per batch     [8,1024,2048]  (V transposed)
//   S  = Q @ K^T per batch                      [8,2048,2048]
//   A  = softmax(S) * 1/32  (in place)
//   out = A @ VT^T per batch ; feature = out + text
// All GEMMs are C[m][n] = sum_k A[m][k] * B[n][k]  (k contiguous everywhere).
// ---------------------------------------------------------------------------

static __device__ float g_Q[16777216];   // 64 MB
static __device__ float g_K[16777216];   // 64 MB
static __device__ float g_VT[16777216];  // 64 MB  [8][1024 v][2048 s]
static __device__ float g_S[33554432];   // 128 MB scores/atten

// ============================ MMA helpers ==================================
__device__ __forceinline__ uint32_t smem_u32(const void* p) {
    uint32_t a;
    asm("{ .reg .u64 t; cvta.to.shared.u64 t, %1; cvt.u32.u64 %0, t; }"
        : "=r"(a) : "l"(p));
    return a;
}

__device__ __forceinline__ void ldsm4(uint32_t* r, uint32_t addr) {
    asm volatile("ldmatrix.sync.aligned.m8n8.x4.shared.b16 {%0,%1,%2,%3}, [%4];"
                 : "=r"(r[0]), "=r"(r[1]), "=r"(r[2]), "=r"(r[3]) : "r"(addr));
}

__device__ __forceinline__ void mma16816(float* d, const uint32_t* a,
                                         uint32_t b0, uint32_t b1) {
    asm volatile(
        "mma.sync.aligned.m16n8k16.row.col.f32.bf16.bf16.f32 "
        "{%0,%1,%2,%3}, {%4,%5,%6,%7}, {%8,%9}, {%0,%1,%2,%3};"
        : "+f"(d[0]), "+f"(d[1]), "+f"(d[2]), "+f"(d[3])
        : "r"(a[0]), "r"(a[1]), "r"(a[2]), "r"(a[3]), "r"(b0), "r"(b1));
}

// fp32 -> (hi bf16, lo bf16) split for 8 consecutive elements
__device__ __forceinline__ void split8(const float4& v0, const float4& v1,
                                       uint4& hi, uint4& lo) {
    float f[8] = {v0.x, v0.y, v0.z, v0.w, v1.x, v1.y, v1.z, v1.w};
    uint32_t h[4], l[4];
#pragma unroll
    for (int j = 0; j < 4; ++j) {
        float a = f[2 * j], b = f[2 * j + 1];
        uint32_t hp;
        asm("cvt.rn.bf16x2.f32 %0, %1, %2;" : "=r"(hp) : "f"(b), "f"(a));
        float ra = __uint_as_float(hp << 16);
        float rb = __uint_as_float(hp & 0xFFFF0000u);
        float la = a - ra, lb = b - rb;
        uint32_t lp;
        asm("cvt.rn.bf16x2.f32 %0, %1, %2;" : "=r"(lp) : "f"(lb), "f"(la));
        h[j] = hp; l[j] = lp;
    }
    hi = make_uint4(h[0], h[1], h[2], h[3]);
    lo = make_uint4(l[0], l[1], l[2], l[3]);
}

// ============================ GEMM kernel ==================================
// CTA 128x128, BK=32 fp32. SMEM regions (bf16, 64B rows, SW64 swizzle):
//   A_hi[2] @ 0      (8 KB/buf)    A_lo[2] @ 16384
//   B_hi[2] @ 32768                B_lo[2] @ 49152
// Epilogue reuses SMEM as fp32 C tile [128][132].
constexpr int SMEM_BYTES = 128 * 132 * 4;   // 67584 (>= 65536 operand area)

// swizzled byte offset within one [128][32bf16] tile
__device__ __forceinline__ uint32_t swz(int row, int colb) {
    return (uint32_t)(row * 64 + (colb ^ ((row & 6) << 3)));
}

// BIASMODE: 0 = none, 1 = per-column, 2 = per-row
template <int BIASMODE, bool AVEPI>
__global__ void __launch_bounds__(256, 1)
tc_gemm(const float* __restrict__ A, const float* __restrict__ B,
        const float* __restrict__ bias, float* __restrict__ C,
        const float* __restrict__ text, float* __restrict__ feat,
        int K, int lda, int ldb, int ldc,
        long long sA, long long sB, long long sC)
{
    extern __shared__ char smem[];
    const uint32_t sb = smem_u32(smem);
    const int tid = threadIdx.x;
    const int lane = tid & 31, warp = tid >> 5;
    const int bx = blockIdx.x, by = blockIdx.y, z = blockIdx.z;

    A += (long long)z * sA;
    B += (long long)z * sB;
    C += (long long)z * sC;
    const float* textz = nullptr;
    float* featz = nullptr;
    if (AVEPI) { textz = text + (long long)z * sC; featz = feat + (long long)z * sC; }

    // ---- loader setup: thread covers 16 consecutive k of one row, A and B
    const int lrow = tid >> 1;            // 0..127
    const int lkh  = (tid & 1) << 4;      // 0 or 16 (k offset)
    const float* aptr = A + (long long)(by * 128 + lrow) * lda + lkh;
    const float* bptr = B + (long long)(bx * 128 + lrow) * ldb + lkh;
    const uint32_t st0 = swz(lrow, lkh * 2);
    const uint32_t st1 = swz(lrow, lkh * 2 + 16);

    // ---- ldmatrix per-lane offsets (within a tile region) ----
    const int wm = (warp >> 2) * 64;      // warp M offset
    const int wn = (warp & 3) * 32;       // warp N offset
    const int a_r = lane & 15;
    const int a_cb = (lane >> 4) << 4;    // 0/16 bytes (k +8)
    const int b_r = ((lane >> 4) << 3) + (lane & 7);
    const int b_cb = (lane & 8) ? 16 : 0;

    uint32_t a_off[4][2], b_off[2][2];
#pragma unroll
    for (int mt = 0; mt < 4; ++mt)
#pragma unroll
        for (int ks = 0; ks < 2; ++ks)
            a_off[mt][ks] = sb + swz(wm + mt * 16 + a_r, ks * 32 + a_cb);
#pragma unroll
    for (int g = 0; g < 2; ++g)
#pragma unroll
        for (int ks = 0; ks < 2; ++ks)
            b_off[g][ks] = sb + 32768u + swz(wn + g * 16 + b_r, ks * 32 + b_cb);

    float acc[4][4][4];
#pragma unroll
    for (int i = 0; i < 4; ++i)
#pragma unroll
        for (int j = 0; j < 4; ++j)
#pragma unroll
            for (int c = 0; c < 4; ++c) acc[i][j][c] = 0.0f;

    const int nk = K >> 5;

    // preload chunk 0
    float4 va0, va1, va2, va3, vb0, vb1, vb2, vb3;
    {
        va0 = *reinterpret_cast<const float4*>(aptr + 0);
        va1 = *reinterpret_cast<const float4*>(aptr + 4);
        va2 = *reinterpret_cast<const float4*>(aptr + 8);
        va3 = *reinterpret_cast<const float4*>(aptr + 12);
        vb0 = *reinterpret_cast<const float4*>(bptr + 0);
        vb1 = *reinterpret_cast<const float4*>(bptr + 4);
        vb2 = *reinterpret_cast<const float4*>(bptr + 8);
        vb3 = *reinterpret_cast<const float4*>(bptr + 12);
    }

    for (int kt = 0; kt < nk; ++kt) {
        const uint32_t bo = (uint32_t)(kt & 1) * 8192u;
        // ---- split current chunk into SMEM ----
        {
            char* base = smem + bo;
            uint4 hi, lo;
            split8(va0, va1, hi, lo);
            *reinterpret_cast<uint4*>(base + st0) = hi;
            *reinterpret_cast<uint4*>(base + 16384 + st0) = lo;
            split8(va2, va3, hi, lo);
            *reinterpret_cast<uint4*>(base + st1) = hi;
            *reinterpret_cast<uint4*>(base + 16384 + st1) = lo;
            split8(vb0, vb1, hi, lo);
            *reinterpret_cast<uint4*>(base + 32768 + st0) = hi;
            *reinterpret_cast<uint4*>(base + 49152 + st0) = lo;
            split8(vb2, vb3, hi, lo);
            *reinterpret_cast<uint4*>(base + 32768 + st1) = hi;
            *reinterpret_cast<uint4*>(base + 49152 + st1) = lo;
        }
        __syncthreads();

        // ---- prefetch next chunk (global, hidden under MMA) ----
        if (kt + 1 < nk) {
            const int k0 = (kt + 1) << 5;
            va0 = *reinterpret_cast<const float4*>(aptr + k0 + 0);
            va1 = *reinterpret_cast<const float4*>(aptr + k0 + 4);
            va2 = *reinterpret_cast<const float4*>(aptr + k0 + 8);
            va3 = *reinterpret_cast<const float4*>(aptr + k0 + 12);
            vb0 = *reinterpret_cast<const float4*>(bptr + k0 + 0);
            vb1 = *reinterpret_cast<const float4*>(bptr + k0 + 4);
            vb2 = *reinterpret_cast<const float4*>(bptr + k0 + 8);
            vb3 = *reinterpret_cast<const float4*>(bptr + k0 + 12);
        }

        // ---- MMA on this chunk: 2 k16 steps x 3 products x 16 tiles ----
#pragma unroll
        for (int ks = 0; ks < 2; ++ks) {
            uint32_t Ah[4][4], Al[4][4], Bh[2][4], Bl[2][4];
#pragma unroll
            for (int mt = 0; mt < 4; ++mt) {
                ldsm4(Ah[mt], a_off[mt][ks] + bo);
                ldsm4(Al[mt], a_off[mt][ks] + bo + 16384u);
            }
#pragma unroll
            for (int g = 0; g < 2; ++g) {
                ldsm4(Bh[g], b_off[g][ks] + bo);
                ldsm4(Bl[g], b_off[g][ks] + bo + 16384u);
            }
#pragma unroll
            for (int p = 0; p < 3; ++p) {
#pragma unroll
                for (int mt = 0; mt < 4; ++mt) {
#pragma unroll
                    for (int nt = 0; nt < 4; ++nt) {
                        const uint32_t* af = (p == 2) ? Al[mt] : Ah[mt];
                        const uint32_t* bf = (p == 1) ? Bl[nt >> 1] : Bh[nt >> 1];
                        mma16816(acc[mt][nt], af, bf[(nt & 1) * 2], bf[(nt & 1) * 2 + 1]);
                    }
                }
            }
        }
        __syncthreads();
    }

    // ---- epilogue: stage C in SMEM (fp32, stride 132), then coalesced write
    float* Cs = reinterpret_cast<float*>(smem);
#pragma unroll
    for (int mt = 0; mt < 4; ++mt) {
#pragma unroll
        for (int nt = 0; nt < 4; ++nt) {
            const int m = wm + mt * 16 + (lane >> 2);
            const int n = wn + nt * 8 + (lane & 3) * 2;
            *reinterpret_cast<float2*>(&Cs[m * 132 + n]) =
                make_float2(acc[mt][nt][0], acc[mt][nt][1]);
            *reinterpret_cast<float2*>(&Cs[(m + 8) * 132 + n]) =
                make_float2(acc[mt][nt][2], acc[mt][nt][3]);
        }
    }
    __syncthreads();

    {
        const int row = tid >> 1;
        const int half = (tid & 1) * 64;
        const long long grow = (long long)(by * 128 + row) * ldc + bx * 128 + half;
        float rbias = 0.0f;
        if (BIASMODE == 2) rbias = bias[by * 128 + row];
#pragma unroll
        for (int j = 0; j < 64; j += 4) {
            float4 v = *reinterpret_cast<const float4*>(&Cs[row * 132 + half + j]);
            if (BIASMODE == 1) {
                float4 bb = *reinterpret_cast<const float4*>(bias + bx * 128 + half + j);
                v.x += bb.x; v.y += bb.y; v.z += bb.z; v.w += bb.w;
            } else if (BIASMODE == 2) {
                v.x += rbias; v.y += rbias; v.z += rbias; v.w += rbias;
            }
            *reinterpret_cast<float4*>(C + grow + j) = v;
            if (AVEPI) {
                float4 t = *reinterpret_cast<const float4*>(textz + grow + j);
                *reinterpret_cast<float4*>(featz + grow + j) =
                    make_float4(v.x + t.x, v.y + t.y, v.z + t.z, v.w + t.w);
            }
        }
    }
}

// ============================ Softmax ======================================
// Row softmax over 2048 cols, in place, fused * (1/sqrt(1024)).
__global__ void __launch_bounds__(256) softmax_k(float* __restrict__ Sm)
{
    __shared__ float red[32];
    const long long row = blockIdx.x;
    float* p = Sm + row * 2048;
    const int t = threadIdx.x;
    const int lane = t & 31, w = t >> 5;

    float4 v0 = reinterpret_cast<const float4*>(p)[t];
    float4 v1 = reinterpret_cast<const float4*>(p)[t + 256];

    float m = fmaxf(fmaxf(fmaxf(v0.x, v0.y), fmaxf(v0.z, v0.w)),
                    fmaxf(fmaxf(v1.x, v1.y), fmaxf(v1.z, v1.w)));
#pragma unroll
    for (int o = 16; o > 0; o >>= 1) m = fmaxf(m, __shfl_xor_sync(0xFFFFFFFFu, m, o));
    if (lane == 0) red[w] = m;
    __syncthreads();
    if (t < 32) {
        float x = (t < 8) ? red[t] : -3.4e38f;
#pragma unroll
        for (int o = 4; o > 0; o >>= 1) x = fmaxf(x, __shfl_xor_sync(0xFFFFFFFFu, x, o));
        if (t == 0) red[0] = x;
    }
    __syncthreads();
    m = red[0];
    __syncthreads();

    float e[8];
    e[0] = expf(v0.x - m); e[1] = expf(v0.y - m); e[2] = expf(v0.z - m); e[3] = expf(v0.w - m);
    e[4] = expf(v1.x - m); e[5] = expf(v1.y - m); e[6] = expf(v1.z - m); e[7] = expf(v1.w - m);
    float s = ((e[0] + e[1]) + (e[2] + e[3])) + ((e[4] + e[5]) + (e[6] + e[7]));
#pragma unroll
    for (int o = 16; o > 0; o >>= 1) s += __shfl_xor_sync(0xFFFFFFFFu, s, o);
    if (lane == 0) red[w] = s;
    __syncthreads();
    if (t < 32) {
        float x = (t < 8) ? red[t] : 0.0f;
#pragma unroll
        for (int o = 4; o > 0; o >>= 1) x += __shfl_xor_sync(0xFFFFFFFFu, x, o);
        if (t == 0) red[0] = x;
    }
    __syncthreads();
    s = red[0];

    const float inv = 0.03125f / s;
    reinterpret_cast<float4*>(p)[t]       = make_float4(e[0]*inv, e[1]*inv, e[2]*inv, e[3]*inv);
    reinterpret_cast<float4*>(p)[t + 256] = make_float4(e[4]*inv, e[5]*inv, e[6]*inv, e[7]*inv);
}

// ============================ Launch =======================================
extern "C" void kernel_launch(void* const* d_in, const int* in_sizes, int n_in,
                              void* d_out, int out_size)
{
    const float* img  = (const float*)d_in[0];
    const float* text = (const float*)d_in[1];
    const float* q_w  = (const float*)d_in[2];
    const float* q_b  = (const float*)d_in[3];
    const float* k_w  = (const float*)d_in[4];
    const float* k_b  = (const float*)d_in[5];
    const float* v_w  = (const float*)d_in[6];
    const float* v_b  = (const float*)d_in[7];
    float* out = (float*)d_out;

    float *gq, *gk, *gvt, *gs;
    cudaGetSymbolAddress((void**)&gq,  g_Q);
    cudaGetSymbolAddress((void**)&gk,  g_K);
    cudaGetSymbolAddress((void**)&gvt, g_VT);
    cudaGetSymbolAddress((void**)&gs,  g_S);

    cudaFuncSetAttribute(tc_gemm<1, false>, cudaFuncAttributeMaxDynamicSharedMemorySize, SMEM_BYTES);
    cudaFuncSetAttribute(tc_gemm<2, false>, cudaFuncAttributeMaxDynamicSharedMemorySize, SMEM_BYTES);
    cudaFuncSetAttribute(tc_gemm<0, false>, cudaFuncAttributeMaxDynamicSharedMemorySize, SMEM_BYTES);
    cudaFuncSetAttribute(tc_gemm<0, true>,  cudaFuncAttributeMaxDynamicSharedMemorySize, SMEM_BYTES);

    // Q = img @ q_w^T + q_b   : M=16384, N=1024, K=1024
    tc_gemm<1, false><<<dim3(8, 128, 1), 256, SMEM_BYTES>>>(
        img, q_w, q_b, gq, nullptr, nullptr, 1024, 1024, 1024, 1024, 0, 0, 0);
    // K = text @ k_w^T + k_b
    tc_gemm<1, false><<<dim3(8, 128, 1), 256, SMEM_BYTES>>>(
        text, k_w, k_b, gk, nullptr, nullptr, 1024, 1024, 1024, 1024, 0, 0, 0);
    // VT[z] = v_w @ text[z]^T + v_b(row) : M=1024, N=2048, K=1024, 8 batches
    tc_gemm<2, false><<<dim3(16, 8, 8), 256, SMEM_BYTES>>>(
        v_w, text, v_b, gvt, nullptr, nullptr, 1024, 1024, 1024, 2048,
        0, 2048LL * 1024, 1024LL * 2048);
    // S[z] = Q[z] @ K[z]^T : M=2048, N=2048, K=1024, 8 batches
    tc_gemm<0, false><<<dim3(16, 16, 8), 256, SMEM_BYTES>>>(
        gq, gk, nullptr, gs, nullptr, nullptr, 1024, 1024, 1024, 2048,
        2048LL * 1024, 2048LL * 1024, 2048LL * 2048);
    // softmax * 1/32, in place
    softmax_k<<<8 * 2048, 256>>>(gs);
    // out[z] = A[z] @ VT[z]^T ; feature = out + text : M=2048, N=1024, K=2048
    tc_gemm<0, true><<<dim3(8, 16, 8), 256, SMEM_BYTES>>>(
        gs, gvt, nullptr, out, text, out + 16777216LL, 2048, 2048, 2048, 1024,
        2048LL * 2048, 1024LL * 2048, 2048LL * 1024);

    (void)in_sizes; (void)n_in; (void)out_size;
}